// round 11
// baseline (speedup 1.0000x reference)
#include <cuda_runtime.h>
#include <cstdint>

// Shapes (fixed): B=128, CIN=16, COUT=16, F=512, N=32, K=2
#define BB   128
#define CI   16
#define CO   16
#define FF   512
#define NN   32
#define NTILES ((BB * FF) / 16)   // 4096 tiles of 16 (b,f)-rows
#define GRID   304                // 2 persistent blocks / SM

// g_W layout [i][c][n] packed u64 (k0,k1);  g_BP [c][n] packed u64 (bv,bv)
__device__ uint64_t g_W[CI * CO * NN];
__device__ uint64_t g_BP[CO * NN];

__device__ __forceinline__ uint64_t pack2(float lo, float hi) {
    uint64_t r;
    asm("mov.b64 %0, {%1, %2};" : "=l"(r) : "f"(lo), "f"(hi));
    return r;
}
__device__ __forceinline__ void ffma2(uint64_t& acc, uint64_t a, uint64_t b) {
    asm("fma.rn.f32x2 %0, %1, %2, %0;" : "+l"(acc) : "l"(a), "l"(b));
}

// ---------------------------------------------------------------------------
// Prologue kernel (proven, separate launch — fusing it spills, R5/6/7/10).
// ---------------------------------------------------------------------------
__global__ void prep_kernel(const float* __restrict__ W1, const float* __restrict__ b1,
                            const float* __restrict__ W2, const float* __restrict__ b2)
{
    const int t = blockIdx.x * blockDim.x + threadIdx.x;
    if (t < CI * CO * NN) {
        const int n = t & 31;
        const int c = (t >> 5) & 15;
        const int i = t >> 9;
        float s0 = 0.f, s1 = 0.f;
        const float2* w1 = (const float2*)(W1 + ((size_t)(n * CI + i) * CO) * 2);
        const float*  w2 = W2 + (size_t)n * CO * CO + c;
#pragma unroll
        for (int o = 0; o < CO; ++o) {
            float2 a = __ldg(w1 + o);
            float  wv = __ldg(w2 + o * CO);
            s0 = fmaf(a.x, wv, s0);
            s1 = fmaf(a.y, wv, s1);
        }
        g_W[(i * CO + c) * NN + n] = pack2(s0, s1);
    }
    if (t < CO * NN) {
        const int n = t & 31;
        const int c = t >> 5;
        float s = __ldg(b2 + n * CO + c);
#pragma unroll
        for (int o = 0; o < CO; ++o)
            s = fmaf(__ldg(b1 + n * CO + o), __ldg(W2 + (size_t)(n * CO + o) * CO + c), s);
        g_BP[c * NN + n] = pack2(s, s);
    }
}

// ---------------------------------------------------------------------------
// Main kernel: vectorized memory ops.
//  lane = (nq = lane&7 owning n=4q..4q+3, rs = lane>>3 row slot)
//  warp = 4 channels x 8 rows (rows g*8 + rs*2 + {0,1})
//  x:   LDG.128 (float4 per lane)   — 32 per warp-tile (was 128 LDG.32)
//  out: STG.128 (float4 per lane)   — 16 per warp-tile (was 32 STG.64)
//  w:   LDS.128 pairs, rs-broadcast
// ---------------------------------------------------------------------------
__global__ __launch_bounds__(256, 2)
void up_kernel(const float* __restrict__ x, float* __restrict__ out)
{
    extern __shared__ uint64_t sW[];          // [i][c][n] u64 : 64 KB
    uint64_t* sBP = sW + CI * CO * NN;        // [c][n]   u64 :  4 KB

    const int tid = threadIdx.x;
    {
        const uint4* gw = (const uint4*)g_W;
        uint4* sw4 = (uint4*)sW;
#pragma unroll
        for (int idx = tid; idx < CI * CO * NN / 2; idx += 256)
            sw4[idx] = gw[idx];
        for (int idx = tid; idx < CO * NN; idx += 256)
            sBP[idx] = g_BP[idx];
    }
    __syncthreads();

    const int lane = tid & 31;
    const int nq   = lane & 7;           // n-quad: n = 4*nq .. 4*nq+3
    const int rs   = lane >> 3;          // row slot: rows rs*2, rs*2+1
    const int warp = tid >> 5;
    const int c0   = (warp & 3) * 4;
    const int g    = warp >> 2;          // row half

    const ulonglong2* wp = (const ulonglong2*)sW;   // 16B units
    const ulonglong2* bp = (const ulonglong2*)sBP;
    const float4* x4 = (const float4*)x;
    float4* o4 = (float4*)out;

    const int bx = blockIdx.x;

    for (int tile = bx; tile < NTILES; tile += GRID) {
        const uint32_t rb = (uint32_t)tile * 16 + g * 8;
        const uint32_t b  = rb >> 9;
        const uint32_t f  = rb & (FF - 1);
        // float4 index of this lane's first row in x
        const uint32_t xi0 = (b * (CI * FF) + f + rs * 2) * (NN / 4) + nq;

        // acc[j][cc][nidx] : j=row in pair, u64 = (k0,k1) for n=4nq+nidx
        uint64_t acc[2][4][4];
#pragma unroll
        for (int cc = 0; cc < 4; ++cc) {
            ulonglong2 b01 = bp[(c0 + cc) * 16 + nq * 2];
            ulonglong2 b23 = bp[(c0 + cc) * 16 + nq * 2 + 1];
#pragma unroll
            for (int j = 0; j < 2; ++j) {
                acc[j][cc][0] = b01.x; acc[j][cc][1] = b01.y;
                acc[j][cc][2] = b23.x; acc[j][cc][3] = b23.y;
            }
        }

        // double-buffered x (float4 per row, 2 rows); parity: 16 i-steps even
        float4 xb[2][2];
        xb[0][0] = x4[xi0];
        xb[0][1] = x4[xi0 + (NN / 4)];

#pragma unroll
        for (int i = 0; i < CI; ++i) {
            // prefetch i+1 (within tile; last iter reloads i=15 harmlessly)
            {
                const int ip = (i < CI - 1) ? (i + 1) : i;
                const uint32_t xip = xi0 + (uint32_t)ip * (FF * NN / 4);
                xb[(i + 1) & 1][0] = x4[xip];
                xb[(i + 1) & 1][1] = x4[xip + (NN / 4)];
            }

            // duplicate-pack x for this i
            uint64_t xd[2][4];
#pragma unroll
            for (int j = 0; j < 2; ++j) {
                const float4 v = xb[i & 1][j];
                xd[j][0] = pack2(v.x, v.x);
                xd[j][1] = pack2(v.y, v.y);
                xd[j][2] = pack2(v.z, v.z);
                xd[j][3] = pack2(v.w, v.w);
            }

#pragma unroll
            for (int cc = 0; cc < 4; ++cc) {
                const ulonglong2 w01 = wp[(i * CO + c0 + cc) * 16 + nq * 2];
                const ulonglong2 w23 = wp[(i * CO + c0 + cc) * 16 + nq * 2 + 1];
#pragma unroll
                for (int j = 0; j < 2; ++j) {
                    ffma2(acc[j][cc][0], xd[j][0], w01.x);
                    ffma2(acc[j][cc][1], xd[j][1], w01.y);
                    ffma2(acc[j][cc][2], xd[j][2], w23.x);
                    ffma2(acc[j][cc][3], xd[j][3], w23.y);
                }
            }
        }

        // stores: out[b, c, f+rs*2+j, 8nq .. 8nq+7] = 2x float4 per (cc,j)
#pragma unroll
        for (int cc = 0; cc < 4; ++cc) {
            const size_t obase = ((size_t)(b * CO + c0 + cc) * FF + f + rs * 2) * 16 + nq * 2;
#pragma unroll
            for (int j = 0; j < 2; ++j) {
                float4 v0, v1;
                v0.x = __ull2float_rd(0), v0.y = 0, v0.z = 0, v0.w = 0; // placeholder (overwritten)
                // (n0k0,n0k1,n1k0,n1k1) = acc[..][0], acc[..][1]
                asm("mov.b64 {%0, %1}, %2;" : "=f"(v0.x), "=f"(v0.y) : "l"(acc[j][cc][0]));
                asm("mov.b64 {%0, %1}, %2;" : "=f"(v0.z), "=f"(v0.w) : "l"(acc[j][cc][1]));
                asm("mov.b64 {%0, %1}, %2;" : "=f"(v1.x), "=f"(v1.y) : "l"(acc[j][cc][2]));
                asm("mov.b64 {%0, %1}, %2;" : "=f"(v1.z), "=f"(v1.w) : "l"(acc[j][cc][3]));
                o4[obase + (size_t)j * 16]     = v0;
                o4[obase + (size_t)j * 16 + 1] = v1;
            }
        }
    }
}

// ---------------------------------------------------------------------------
extern "C" void kernel_launch(void* const* d_in, const int* in_sizes, int n_in,
                              void* d_out, int out_size)
{
    const float* x  = (const float*)d_in[0];
    const float* W1 = (const float*)d_in[1];
    const float* b1 = (const float*)d_in[2];
    const float* W2 = (const float*)d_in[3];
    const float* b2 = (const float*)d_in[4];
    float* out = (float*)d_out;

    prep_kernel<<<32, 256>>>(W1, b1, W2, b2);

    const int smem_bytes = CI * CO * NN * 8 + CO * NN * 8;   // 68 KB
    cudaFuncSetAttribute(up_kernel, cudaFuncAttributeMaxDynamicSharedMemorySize,
                         smem_bytes);
    up_kernel<<<GRID, 256, smem_bytes>>>(x, out);
}

// round 12
// speedup vs baseline: 1.0115x; 1.0115x over previous
#include <cuda_runtime.h>
#include <cstdint>

// Shapes (fixed): B=128, CIN=16, COUT=16, F=512, N=32, K=2
#define BB   128
#define CI   16
#define CO   16
#define FF   512
#define NN   32
#define NTILES ((BB * FF) / 16)   // 4096 tiles of 16 (b,f)-rows
#define GRID   304                // 2 persistent blocks / SM

// g_W layout [i][c][n] packed u64 (k0,k1);  g_BP [c][n] packed u64 (bv,bv)
__device__ uint64_t g_W[CI * CO * NN];
__device__ uint64_t g_BP[CO * NN];

__device__ __forceinline__ uint64_t pack2(float lo, float hi) {
    uint64_t r;
    asm("mov.b64 %0, {%1, %2};" : "=l"(r) : "f"(lo), "f"(hi));
    return r;
}
__device__ __forceinline__ void ffma2(uint64_t& acc, uint64_t a, uint64_t b) {
    asm("fma.rn.f32x2 %0, %1, %2, %0;" : "+l"(acc) : "l"(a), "l"(b));
}

// ---------------------------------------------------------------------------
// Prologue kernel (separate launch — fusing it spills: R5/6/7/10).
// ---------------------------------------------------------------------------
__global__ void prep_kernel(const float* __restrict__ W1, const float* __restrict__ b1,
                            const float* __restrict__ W2, const float* __restrict__ b2)
{
    const int t = blockIdx.x * blockDim.x + threadIdx.x;
    if (t < CI * CO * NN) {
        const int n = t & 31;
        const int c = (t >> 5) & 15;
        const int i = t >> 9;
        float s0 = 0.f, s1 = 0.f;
        const float2* w1 = (const float2*)(W1 + ((size_t)(n * CI + i) * CO) * 2);
        const float*  w2 = W2 + (size_t)n * CO * CO + c;
#pragma unroll
        for (int o = 0; o < CO; ++o) {
            float2 a = __ldg(w1 + o);
            float  wv = __ldg(w2 + o * CO);
            s0 = fmaf(a.x, wv, s0);
            s1 = fmaf(a.y, wv, s1);
        }
        g_W[(i * CO + c) * NN + n] = pack2(s0, s1);
    }
    if (t < CO * NN) {
        const int n = t & 31;
        const int c = t >> 5;
        float s = __ldg(b2 + n * CO + c);
#pragma unroll
        for (int o = 0; o < CO; ++o)
            s = fmaf(__ldg(b1 + n * CO + o), __ldg(W2 + (size_t)(n * CO + o) * CO + c), s);
        g_BP[c * NN + n] = pack2(s, s);
    }
}

// ---------------------------------------------------------------------------
// Main kernel: R11's (numerically verified) vectorized layout, restructured
// np-outer/cc-inner so the transient pack set is 4 regs instead of 16.
//  lane = (nq = lane&7 -> n=4nq..4nq+3, rs = lane>>3 -> rows rs*2, rs*2+1)
//  warp = 4 channels x 8 rows;  x: LDG.128;  out: STG.128;  w: LDS.128 bcast
// ---------------------------------------------------------------------------
__global__ __launch_bounds__(256, 2)
void up_kernel(const float* __restrict__ x, float* __restrict__ out)
{
    extern __shared__ uint64_t sW[];          // [i][c][n] u64 : 64 KB
    uint64_t* sBP = sW + CI * CO * NN;        // [c][n]   u64 :  4 KB

    const int tid = threadIdx.x;
    {
        const uint4* gw = (const uint4*)g_W;
        uint4* sw4 = (uint4*)sW;
#pragma unroll
        for (int idx = tid; idx < CI * CO * NN / 2; idx += 256)
            sw4[idx] = gw[idx];
        for (int idx = tid; idx < CO * NN; idx += 256)
            sBP[idx] = g_BP[idx];
    }
    __syncthreads();

    const int lane = tid & 31;
    const int nq   = lane & 7;           // n-quad
    const int rs   = lane >> 3;          // row slot
    const int warp = tid >> 5;
    const int c0   = (warp & 3) * 4;
    const int g    = warp >> 2;          // row half

    const ulonglong2* wp = (const ulonglong2*)sW;   // 16B units
    const ulonglong2* bp = (const ulonglong2*)sBP;
    const float4* x4 = (const float4*)x;
    float4* o4 = (float4*)out;

    const int bx = blockIdx.x;

    // float4 x index of this lane's first row for the first tile
    uint32_t xi0;
    {
        const uint32_t rb = (uint32_t)bx * 16 + g * 8;
        xi0 = ((rb >> 9) * (CI * FF) + (rb & (FF - 1)) + rs * 2) * (NN / 4) + nq;
    }

    // double-buffered x rows (2 float4 per slot); 16 i-steps (even) -> parity
    // tile-invariant: slot 0 holds i=0 at every tile entry.
    float4 xb[2][2];
    xb[0][0] = x4[xi0];
    xb[0][1] = x4[xi0 + (NN / 4)];

    for (int tile = bx; tile < NTILES; tile += GRID) {
        const uint32_t rb = (uint32_t)tile * 16 + g * 8;
        const uint32_t b  = rb >> 9;
        const uint32_t f  = rb & (FF - 1);

        // next tile's x base (clamped; in-bounds, unused values on last tile)
        const int tn = (tile + GRID < NTILES) ? (tile + GRID) : tile;
        const uint32_t rbn = (uint32_t)tn * 16 + g * 8;
        const uint32_t xi0n = ((rbn >> 9) * (CI * FF) + (rbn & (FF - 1)) + rs * 2) * (NN / 4) + nq;

        // acc[j][cc][nidx]: j = row in pair, u64 = (k0,k1) for n = 4nq+nidx
        uint64_t acc[2][4][4];
#pragma unroll
        for (int cc = 0; cc < 4; ++cc) {
            const ulonglong2 b01 = bp[(c0 + cc) * 16 + nq * 2];
            const ulonglong2 b23 = bp[(c0 + cc) * 16 + nq * 2 + 1];
#pragma unroll
            for (int j = 0; j < 2; ++j) {
                acc[j][cc][0] = b01.x; acc[j][cc][1] = b01.y;
                acc[j][cc][2] = b23.x; acc[j][cc][3] = b23.y;
            }
        }

#pragma unroll
        for (int i = 0; i < CI; ++i) {
            // prefetch i+1; at i=15 fetch next tile's i=0 into slot 0
            {
                const uint32_t xip = (i < CI - 1)
                                   ? (xi0 + (uint32_t)(i + 1) * (FF * NN / 4))
                                   : xi0n;
                xb[(i + 1) & 1][0] = x4[xip];
                xb[(i + 1) & 1][1] = x4[xip + (NN / 4)];
            }

            const float4 v0 = xb[i & 1][0];
            const float4 v1 = xb[i & 1][1];

            // n-pair 0: n = 4nq, 4nq+1  (components x, y)
            {
                const uint64_t xd00 = pack2(v0.x, v0.x);
                const uint64_t xd01 = pack2(v0.y, v0.y);
                const uint64_t xd10 = pack2(v1.x, v1.x);
                const uint64_t xd11 = pack2(v1.y, v1.y);
#pragma unroll
                for (int cc = 0; cc < 4; ++cc) {
                    const ulonglong2 w = wp[(i * CO + c0 + cc) * 16 + nq * 2];
                    ffma2(acc[0][cc][0], xd00, w.x);
                    ffma2(acc[0][cc][1], xd01, w.y);
                    ffma2(acc[1][cc][0], xd10, w.x);
                    ffma2(acc[1][cc][1], xd11, w.y);
                }
            }
            // n-pair 1: n = 4nq+2, 4nq+3  (components z, w)
            {
                const uint64_t xd00 = pack2(v0.z, v0.z);
                const uint64_t xd01 = pack2(v0.w, v0.w);
                const uint64_t xd10 = pack2(v1.z, v1.z);
                const uint64_t xd11 = pack2(v1.w, v1.w);
#pragma unroll
                for (int cc = 0; cc < 4; ++cc) {
                    const ulonglong2 w = wp[(i * CO + c0 + cc) * 16 + nq * 2 + 1];
                    ffma2(acc[0][cc][2], xd00, w.x);
                    ffma2(acc[0][cc][3], xd01, w.y);
                    ffma2(acc[1][cc][2], xd10, w.x);
                    ffma2(acc[1][cc][3], xd11, w.y);
                }
            }
        }

        // stores (verified in R11): out[b, c, f+rs*2+j, 8nq .. 8nq+7]
#pragma unroll
        for (int cc = 0; cc < 4; ++cc) {
            const size_t obase = ((size_t)(b * CO + c0 + cc) * FF + f + rs * 2) * 16 + nq * 2;
#pragma unroll
            for (int j = 0; j < 2; ++j) {
                float4 u0, u1;
                asm("mov.b64 {%0, %1}, %2;" : "=f"(u0.x), "=f"(u0.y) : "l"(acc[j][cc][0]));
                asm("mov.b64 {%0, %1}, %2;" : "=f"(u0.z), "=f"(u0.w) : "l"(acc[j][cc][1]));
                asm("mov.b64 {%0, %1}, %2;" : "=f"(u1.x), "=f"(u1.y) : "l"(acc[j][cc][2]));
                asm("mov.b64 {%0, %1}, %2;" : "=f"(u1.z), "=f"(u1.w) : "l"(acc[j][cc][3]));
                o4[obase + (size_t)j * 16]     = u0;
                o4[obase + (size_t)j * 16 + 1] = u1;
            }
        }

        xi0 = xi0n;
    }
}

// ---------------------------------------------------------------------------
extern "C" void kernel_launch(void* const* d_in, const int* in_sizes, int n_in,
                              void* d_out, int out_size)
{
    const float* x  = (const float*)d_in[0];
    const float* W1 = (const float*)d_in[1];
    const float* b1 = (const float*)d_in[2];
    const float* W2 = (const float*)d_in[3];
    const float* b2 = (const float*)d_in[4];
    float* out = (float*)d_out;

    prep_kernel<<<32, 256>>>(W1, b1, W2, b2);

    const int smem_bytes = CI * CO * NN * 8 + CO * NN * 8;   // 68 KB
    cudaFuncSetAttribute(up_kernel, cudaFuncAttributeMaxDynamicSharedMemorySize,
                         smem_bytes);
    up_kernel<<<GRID, 256, smem_bytes>>>(x, out);
}

// round 13
// speedup vs baseline: 1.5588x; 1.5411x over previous
#include <cuda_runtime.h>
#include <cstdint>

// Shapes (fixed): B=128, CIN=16, COUT=16, F=512, N=32, K=2
#define BB   128
#define CI   16
#define CO   16
#define FF   512
#define NN   32
#define NTILES ((BB * FF) / 16)   // 4096 tiles of 16 (b,f)-rows
#define GRID   304                // 2 persistent blocks / SM

// g_W: [i][c][np][4] floats = {k0n0, k0n1, k1n0, k1n1}  (64 KB)
// g_B: [c][n] floats (2 KB)
__device__ float g_W[CI * CO * 16 * 4];
__device__ float g_B[CO * NN];

__device__ __forceinline__ void ffma2(uint64_t& acc, uint64_t a, uint64_t b) {
    asm("fma.rn.f32x2 %0, %1, %2, %0;" : "+l"(acc) : "l"(a), "l"(b));
}

// ---------------------------------------------------------------------------
// Prologue kernel (separate launch — fusing spills: R5/6/7/10).
// Weff[n,i,c,k] = sum_o W1[n,i,o,k] * W2[n,o,c]
// ---------------------------------------------------------------------------
__global__ void prep_kernel(const float* __restrict__ W1, const float* __restrict__ b1,
                            const float* __restrict__ W2, const float* __restrict__ b2)
{
    const int t = blockIdx.x * blockDim.x + threadIdx.x;
    if (t < CI * CO * NN) {
        const int n = t & 31;
        const int c = (t >> 5) & 15;
        const int i = t >> 9;
        float s0 = 0.f, s1 = 0.f;
        const float2* w1 = (const float2*)(W1 + ((size_t)(n * CI + i) * CO) * 2);
        const float*  w2 = W2 + (size_t)n * CO * CO + c;
#pragma unroll
        for (int o = 0; o < CO; ++o) {
            float2 a = __ldg(w1 + o);
            float  wv = __ldg(w2 + o * CO);
            s0 = fmaf(a.x, wv, s0);
            s1 = fmaf(a.y, wv, s1);
        }
        // n-pair layout: {k0n0, k0n1, k1n0, k1n1}
        const int np = n >> 1, h = n & 1;
        const int base = ((i * CO + c) * 16 + np) * 4;
        g_W[base + h]     = s0;    // k0, position h in pair
        g_W[base + 2 + h] = s1;    // k1
    }
    if (t < CO * NN) {
        const int n = t & 31;
        const int c = t >> 5;
        float s = __ldg(b2 + n * CO + c);
#pragma unroll
        for (int o = 0; o < CO; ++o)
            s = fmaf(__ldg(b1 + n * CO + o), __ldg(W2 + (size_t)(n * CO + o) * CO + c), s);
        g_B[c * NN + n] = s;
    }
}

// ---------------------------------------------------------------------------
// Main kernel. acc paired over n (not k): x operand = raw float2 load, no
// duplication movs, no pack transients.
//  lane = (np = lane&15 -> n-pair, rs = lane>>4 -> rows rs*4 .. rs*4+3)
//  warp = 4 channels x 8 rows
//  x: LDG.64 (64/warp-tile)  w: LDS.128 bcast (64)  out: STG.128 (16)
// ---------------------------------------------------------------------------
__global__ __launch_bounds__(256, 2)
void up_kernel(const float* __restrict__ x, float* __restrict__ out)
{
    extern __shared__ ulonglong2 sW[];        // [i][c][np] {k0pair, k1pair} : 64 KB
    uint64_t* sB = (uint64_t*)(sW + CI * CO * 16);  // [c][np] (b_n0, b_n1) : 2 KB

    const int tid = threadIdx.x;
    {
        const uint4* gw = (const uint4*)g_W;
        uint4* sw4 = (uint4*)sW;
#pragma unroll
        for (int idx = tid; idx < CI * CO * 16; idx += 256)
            sw4[idx] = gw[idx];
        const uint64_t* gb = (const uint64_t*)g_B;
        for (int idx = tid; idx < CO * 16; idx += 256)
            sB[idx] = gb[idx];
    }
    __syncthreads();

    const int lane = tid & 31;
    const int np   = lane & 15;          // n-pair: n0 = 2np, n1 = 2np+1
    const int rs   = lane >> 4;          // row slot: rows rs*4 .. rs*4+3
    const int warp = tid >> 5;
    const int c0   = (warp & 3) * 4;     // c-quarter
    const int g    = warp >> 2;          // row half

    const uint64_t* x2 = (const uint64_t*)x;   // float2 units
    float4* o4 = (float4*)out;

    for (int tile = blockIdx.x; tile < NTILES; tile += GRID) {
        const uint32_t rb = (uint32_t)tile * 16 + g * 8 + rs * 4;  // lane's first row
        const uint32_t b  = rb >> 9;
        const uint32_t fr = rb & (FF - 1);
        // x u64 index of (i, row fr+j): ((b*CI + i)*FF + fr + j)*16 + np
        const uint32_t xbase = (b * (CI * FF) + fr) * 16 + np;

        // acc0[j][cc] = (n0k0, n1k0); acc1[j][cc] = (n0k1, n1k1)
        uint64_t acc0[4][4], acc1[4][4];
#pragma unroll
        for (int cc = 0; cc < 4; ++cc) {
            const uint64_t bv = sB[(c0 + cc) * 16 + np];
#pragma unroll
            for (int j = 0; j < 4; ++j) { acc0[j][cc] = bv; acc1[j][cc] = bv; }
        }

        // double-buffered raw float2 rows; slot 0 = i=0
        uint64_t xq[2][4];
#pragma unroll
        for (int j = 0; j < 4; ++j)
            xq[0][j] = x2[xbase + j * 16];

#pragma unroll
        for (int i = 0; i < CI; ++i) {
            ulonglong2 w[4];
#pragma unroll
            for (int cc = 0; cc < 4; ++cc)
                w[cc] = sW[(i * CO + c0 + cc) * 16 + np];

            if (i < CI - 1) {
                const uint32_t xp = xbase + (uint32_t)(i + 1) * (FF * 16);
#pragma unroll
                for (int j = 0; j < 4; ++j)
                    xq[(i + 1) & 1][j] = x2[xp + j * 16];
            }

#pragma unroll
            for (int j = 0; j < 4; ++j) {
                const uint64_t xv = xq[i & 1][j];   // (x_n0, x_n1) raw
#pragma unroll
                for (int cc = 0; cc < 4; ++cc) {
                    ffma2(acc0[j][cc], xv, w[cc].x);   // k0 n-pair weights
                    ffma2(acc1[j][cc], xv, w[cc].y);   // k1 n-pair weights
                }
            }
        }

        // stores: out[b, c0+cc, fr+j, 4np .. 4np+3] = (n0k0, n0k1, n1k0, n1k1)
#pragma unroll
        for (int cc = 0; cc < 4; ++cc) {
            const uint32_t obase = ((b * CO + c0 + cc) * FF + fr) * 16 + np;
#pragma unroll
            for (int j = 0; j < 4; ++j) {
                float4 u;
                asm("mov.b64 {%0, %1}, %2;" : "=f"(u.x), "=f"(u.z) : "l"(acc0[j][cc]));
                asm("mov.b64 {%0, %1}, %2;" : "=f"(u.y), "=f"(u.w) : "l"(acc1[j][cc]));
                o4[obase + j * 16] = u;
            }
        }
    }
}

// ---------------------------------------------------------------------------
extern "C" void kernel_launch(void* const* d_in, const int* in_sizes, int n_in,
                              void* d_out, int out_size)
{
    const float* x  = (const float*)d_in[0];
    const float* W1 = (const float*)d_in[1];
    const float* b1 = (const float*)d_in[2];
    const float* W2 = (const float*)d_in[3];
    const float* b2 = (const float*)d_in[4];
    float* out = (float*)d_out;

    prep_kernel<<<32, 256>>>(W1, b1, W2, b2);

    const int smem_bytes = CI * CO * 16 * 16 + CO * 16 * 8;   // 64 KB + 2 KB
    cudaFuncSetAttribute(up_kernel, cudaFuncAttributeMaxDynamicSharedMemorySize,
                         smem_bytes);
    up_kernel<<<GRID, 256, smem_bytes>>>(x, out);
}

// round 14
// speedup vs baseline: 3.7022x; 2.3750x over previous
#include <cuda_runtime.h>
#include <cstdint>

// Shapes (fixed): B=128, CIN=16, COUT=16, F=512, N=32, K=2
#define BB   128
#define CI   16
#define CO   16
#define FF   512
#define NN   32
#define NTILES ((BB * FF) / 16)   // 4096 tiles of 16 (b,f)-rows
#define GRID   304                // 2 persistent blocks / SM

// smem: sW [i][c][n] u64 (k0,k1) = 64 KB ; sBias [c][n] float = 2 KB
#define SW_CNT   (CI * CO * NN)
#define SMEM_BYTES (SW_CNT * 8 + CO * NN * 4)

__device__ __forceinline__ uint64_t pack2(float lo, float hi) {
    uint64_t r;
    asm("mov.b64 %0, {%1, %2};" : "=l"(r) : "f"(lo), "f"(hi));
    return r;
}
__device__ __forceinline__ void ffma2(uint64_t& acc, uint64_t a, uint64_t b) {
    asm("fma.rn.f32x2 %0, %1, %2, %0;" : "+l"(acc) : "l"(a), "l"(b));
}

// ---------------------------------------------------------------------------
// Weight fold (R7's verified-correct routine), noinline to isolate its
// register allocation from the main loop's.
// ---------------------------------------------------------------------------
__device__ __noinline__ void build_weights(uint64_t* sW, float* sBias,
                                           const float* W1, const float* b1,
                                           const float* W2, const float* b2,
                                           int tid)
{
    const int c  = tid >> 4;
    const int np = tid & 15;
    const int n0 = 2 * np, n1 = n0 + 1;
    float w2a[16], w2b[16];
#pragma unroll
    for (int o = 0; o < CO; ++o) {
        w2a[o] = __ldg(W2 + (n0 * CO + o) * CO + c);
        w2b[o] = __ldg(W2 + (n1 * CO + o) * CO + c);
    }
    float ba = __ldg(b2 + n0 * CO + c);
    float bb = __ldg(b2 + n1 * CO + c);
#pragma unroll
    for (int o = 0; o < CO; ++o) {
        ba = fmaf(__ldg(b1 + n0 * CO + o), w2a[o], ba);
        bb = fmaf(__ldg(b1 + n1 * CO + o), w2b[o], bb);
    }
    sBias[c * NN + n0] = ba;
    sBias[c * NN + n1] = bb;
#pragma unroll
    for (int i = 0; i < CI; ++i) {
        float s0x = 0.f, s0y = 0.f, s1x = 0.f, s1y = 0.f;
        const float2* wa = (const float2*)(W1 + ((size_t)(n0 * CI + i) * CO) * 2);
        const float2* wb = (const float2*)(W1 + ((size_t)(n1 * CI + i) * CO) * 2);
#pragma unroll
        for (int o = 0; o < CO; ++o) {
            float2 a  = __ldg(wa + o);
            float2 bq = __ldg(wb + o);
            s0x = fmaf(a.x,  w2a[o], s0x);   // n0,k0
            s0y = fmaf(a.y,  w2a[o], s0y);   // n0,k1
            s1x = fmaf(bq.x, w2b[o], s1x);   // n1,k0
            s1y = fmaf(bq.y, w2b[o], s1y);   // n1,k1
        }
        sW[(i * CO + c) * NN + n0] = pack2(s0x, s0y);
        sW[(i * CO + c) * NN + n1] = pack2(s1x, s1y);
    }
}

// ---------------------------------------------------------------------------
// Main kernel: fused fold + VERBATIM R2 main body (the proven 84us loop —
// no dnext, no cross-tile prefetch, no ring >2, no clamped pointers).
// ---------------------------------------------------------------------------
__global__ __launch_bounds__(256, 2)
void fused_kernel(const float* __restrict__ x,
                  const float* __restrict__ W1, const float* __restrict__ b1,
                  const float* __restrict__ W2, const float* __restrict__ b2,
                  float* __restrict__ out)
{
    extern __shared__ uint64_t sW[];          // [i][c][n] packed (k0,k1)
    float* sBias = (float*)(sW + SW_CNT);     // [c][n]

    build_weights(sW, sBias, W1, b1, W2, b2, threadIdx.x);
    __syncthreads();

    // ======= from here on: byte-for-byte the R2 main body =======
    const int tid  = threadIdx.x;
    const int lane = tid & 31;           // n
    const int warp = tid >> 5;
    const int q    = warp & 3;           // c-quarter
    const int g    = warp >> 2;          // row-group (0,1)
    const int c0   = q * 4;

    uint64_t bp[4];
#pragma unroll
    for (int cc = 0; cc < 4; ++cc) {
        float bv = sBias[(c0 + cc) * NN + lane];
        bp[cc] = pack2(bv, bv);
    }

    const uint64_t* wbase = sW + c0 * NN + lane;   // + i*CO*NN + cc*NN

    for (int tile = blockIdx.x; tile < NTILES; tile += GRID) {
        const int rowbase = tile * 16 + g * 8;     // 8 consecutive f rows, same b
        const int b = rowbase >> 9;
        const int f = rowbase & (FF - 1);

        const float* xp = x + ((size_t)b * CI * FF + f) * NN + lane;
        uint64_t*    op = (uint64_t*)out + (((size_t)b * CO + c0) * FF + f) * NN + lane;

        uint64_t acc[8][4];
#pragma unroll
        for (int cc = 0; cc < 4; ++cc)
#pragma unroll
            for (int r = 0; r < 8; ++r) acc[r][cc] = bp[cc];

        // double-buffered x: load i+1 while doing i's FMAs
        uint64_t xv[2][8];
#pragma unroll
        for (int r = 0; r < 8; ++r) {
            float v = __ldg(xp + (size_t)r * NN);
            xv[0][r] = pack2(v, v);
        }

#pragma unroll
        for (int i = 0; i < CI; ++i) {
            uint64_t w[4];
#pragma unroll
            for (int cc = 0; cc < 4; ++cc)
                w[cc] = wbase[(i * CO + cc) * NN];

            if (i + 1 < CI) {
#pragma unroll
                for (int r = 0; r < 8; ++r) {
                    float v = __ldg(xp + ((size_t)(i + 1) * FF + r) * NN);
                    xv[(i + 1) & 1][r] = pack2(v, v);
                }
            }

#pragma unroll
            for (int cc = 0; cc < 4; ++cc)
#pragma unroll
                for (int r = 0; r < 8; ++r)
                    ffma2(acc[r][cc], xv[i & 1][r], w[cc]);
        }

        // out[b, c0+cc, f+r, 2n+k] as float2 — coalesced 256B stores
#pragma unroll
        for (int cc = 0; cc < 4; ++cc)
#pragma unroll
            for (int r = 0; r < 8; ++r)
                op[((size_t)cc * FF + r) * NN] = acc[r][cc];
    }
}

// ---------------------------------------------------------------------------
extern "C" void kernel_launch(void* const* d_in, const int* in_sizes, int n_in,
                              void* d_out, int out_size)
{
    const float* x  = (const float*)d_in[0];
    const float* W1 = (const float*)d_in[1];
    const float* b1 = (const float*)d_in[2];
    const float* W2 = (const float*)d_in[3];
    const float* b2 = (const float*)d_in[4];
    float* out = (float*)d_out;

    cudaFuncSetAttribute(fused_kernel, cudaFuncAttributeMaxDynamicSharedMemorySize,
                         SMEM_BYTES);
    fused_kernel<<<GRID, 256, SMEM_BYTES>>>(x, W1, b1, W2, b2, out);
}

// round 15
// speedup vs baseline: 8.8046x; 2.3782x over previous
#include <cuda_runtime.h>
#include <cstdint>

// Shapes (fixed): B=128, CIN=16, COUT=16, F=512, N=32, K=2
#define BB   128
#define CI   16
#define CO   16
#define FF   512
#define NN   32
#define NTILES ((BB * FF) / 16)   // 4096 tiles of 16 (b,f)-rows
#define GRID   304                // 2 persistent blocks / SM

// Effective weights: Weff[n,i,c,k] = sum_o W1[n,i,o,k]*W2[n,o,c]
// g_W layout [i][c][n] packed u64 (k0,k1);  g_Bias [c][n]
__device__ uint64_t g_W[CI * CO * NN];
__device__ float    g_Bias[CO * NN];

__device__ __forceinline__ uint64_t pack2(float lo, float hi) {
    uint64_t r;
    asm("mov.b64 %0, {%1, %2};" : "=l"(r) : "f"(lo), "f"(hi));
    return r;
}
__device__ __forceinline__ void ffma2(uint64_t& acc, uint64_t a, uint64_t b) {
    asm("fma.rn.f32x2 %0, %1, %2, %0;" : "+l"(acc) : "l"(a), "l"(b));
}
__device__ __forceinline__ void stcs64(uint64_t* p, uint64_t v) {
    asm volatile("st.global.cs.b64 [%0], %1;" :: "l"(p), "l"(v) : "memory");
}

// ---------------------------------------------------------------------------
// Prologue kernel (separate launch — every fusion attempt spilled: R5-R7,
// R10, R14). One thread per (i,c,n).
// ---------------------------------------------------------------------------
__global__ void prep_kernel(const float* __restrict__ W1, const float* __restrict__ b1,
                            const float* __restrict__ W2, const float* __restrict__ b2)
{
    const int t = blockIdx.x * blockDim.x + threadIdx.x;
    if (t < CI * CO * NN) {
        const int n = t & 31;
        const int c = (t >> 5) & 15;
        const int i = t >> 9;
        float s0 = 0.f, s1 = 0.f;
        const float2* w1 = (const float2*)(W1 + ((size_t)(n * CI + i) * CO) * 2);
        const float*  w2 = W2 + (size_t)n * CO * CO + c;
#pragma unroll
        for (int o = 0; o < CO; ++o) {
            float2 a = __ldg(w1 + o);
            float  wv = __ldg(w2 + o * CO);
            s0 = fmaf(a.x, wv, s0);
            s1 = fmaf(a.y, wv, s1);
        }
        g_W[(i * CO + c) * NN + n] = pack2(s0, s1);
    }
    if (t < CO * NN) {
        const int n = t & 31;
        const int c = t >> 5;
        float s = __ldg(b2 + n * CO + c);
#pragma unroll
        for (int o = 0; o < CO; ++o)
            s = fmaf(__ldg(b1 + n * CO + o), __ldg(W2 + (size_t)(n * CO + o) * CO + c), s);
        g_Bias[c * NN + n] = s;
    }
}

// ---------------------------------------------------------------------------
// Main kernel — the proven R2 body (124 regs, 84us). Only register-neutral
// edits vs R2: (1) prefetch LDGs issued before the weight LDS in each
// i-iteration, (2) streaming stores.
// ---------------------------------------------------------------------------
__global__ __launch_bounds__(256, 2)
void up_kernel(const float* __restrict__ x, float* __restrict__ out)
{
    extern __shared__ uint64_t sW[];   // 8192 x 8B = 64 KB, layout [i][c][n]
    float* sBias = (float*)(sW + CI * CO * NN);

    const int tid = threadIdx.x;

    // cooperative one-time stage of Weff + bias (16B vector copies)
    {
        const uint4* gw = (const uint4*)g_W;
        uint4* sw4 = (uint4*)sW;
#pragma unroll
        for (int idx = tid; idx < CI * CO * NN / 2; idx += 256)
            sw4[idx] = gw[idx];
        for (int idx = tid; idx < CO * NN; idx += 256)
            sBias[idx] = g_Bias[idx];
    }
    __syncthreads();

    const int lane = tid & 31;           // n
    const int warp = tid >> 5;
    const int q    = warp & 3;           // c-quarter
    const int g    = warp >> 2;          // row-group (0,1)
    const int c0   = q * 4;

    // bias in registers, packed (k0,k1) duplicated
    uint64_t bp[4];
#pragma unroll
    for (int cc = 0; cc < 4; ++cc) {
        float bv = sBias[(c0 + cc) * NN + lane];
        bp[cc] = pack2(bv, bv);
    }

    const uint64_t* wbase = sW + c0 * NN + lane;   // + i*CO*NN + cc*NN

    for (int tile = blockIdx.x; tile < NTILES; tile += GRID) {
        const int rowbase = tile * 16 + g * 8;     // 8 consecutive f rows, same b
        const int b = rowbase >> 9;
        const int f = rowbase & (FF - 1);

        const float* xp = x + ((size_t)b * CI * FF + f) * NN + lane;
        uint64_t*    op = (uint64_t*)out + (((size_t)b * CO + c0) * FF + f) * NN + lane;

        uint64_t acc[8][4];
#pragma unroll
        for (int cc = 0; cc < 4; ++cc)
#pragma unroll
            for (int r = 0; r < 8; ++r) acc[r][cc] = bp[cc];

        // double-buffered x: load i+1 while doing i's FMAs
        uint64_t xv[2][8];
#pragma unroll
        for (int r = 0; r < 8; ++r) {
            float v = __ldg(xp + (size_t)r * NN);
            xv[0][r] = pack2(v, v);
        }

#pragma unroll
        for (int i = 0; i < CI; ++i) {
            // (reordered vs R2) prefetch i+1 FIRST for extra LDG lead time
            if (i + 1 < CI) {
#pragma unroll
                for (int r = 0; r < 8; ++r) {
                    float v = __ldg(xp + ((size_t)(i + 1) * FF + r) * NN);
                    xv[(i + 1) & 1][r] = pack2(v, v);
                }
            }

            uint64_t w[4];
#pragma unroll
            for (int cc = 0; cc < 4; ++cc)
                w[cc] = wbase[(i * CO + cc) * NN];

#pragma unroll
            for (int cc = 0; cc < 4; ++cc)
#pragma unroll
                for (int r = 0; r < 8; ++r)
                    ffma2(acc[r][cc], xv[i & 1][r], w[cc]);
        }

        // out[b, c0+cc, f+r, 2n+k] as float2 — coalesced 256B streaming stores
#pragma unroll
        for (int cc = 0; cc < 4; ++cc)
#pragma unroll
            for (int r = 0; r < 8; ++r)
                stcs64(op + ((size_t)cc * FF + r) * NN, acc[r][cc]);
    }
}

// ---------------------------------------------------------------------------
extern "C" void kernel_launch(void* const* d_in, const int* in_sizes, int n_in,
                              void* d_out, int out_size)
{
    const float* x  = (const float*)d_in[0];
    const float* W1 = (const float*)d_in[1];
    const float* b1 = (const float*)d_in[2];
    const float* W2 = (const float*)d_in[3];
    const float* b2 = (const float*)d_in[4];
    float* out = (float*)d_out;

    prep_kernel<<<64, 128>>>(W1, b1, W2, b2);

    const int smem_bytes = CI * CO * NN * 8 + CO * NN * 4;   // 64 KB + 2 KB
    cudaFuncSetAttribute(up_kernel, cudaFuncAttributeMaxDynamicSharedMemorySize,
                         smem_bytes);
    up_kernel<<<GRID, 256, smem_bytes>>>(x, out);
}